// round 1
// baseline (speedup 1.0000x reference)
#include <cuda_runtime.h>
#include <cstdint>

// ---------------- problem constants ----------------
#define NB      8
#define LQ      2500
#define DM      256
#define NH      8
#define NL      4
#define NP      8
#define NZ      4
#define DH      32
#define LEN_IN  14960

// scratch (static device allocations are allowed)
__device__ float g_value[(size_t)NB * LEN_IN * DM];          // 119680 x 256
__device__ float g_off  [(size_t)NB * LQ * NH * NL * NP * 2]; // 20000 x 512
__device__ float g_awl  [(size_t)NB * LQ * NH * NL * NP];     // 20000 x 256

// ---------------- fp32 tiled GEMM with bias: C = A(MxK) * B(KxN) + bias ----------------
// BM=128, BN=128, BK=16, 256 threads, 8x8 per thread. N % 128 == 0, K % 16 == 0 assumed.
__global__ __launch_bounds__(256)
void sgemm_bias(const float* __restrict__ A,
                const float* __restrict__ B,
                const float* __restrict__ bias,
                float* __restrict__ C,
                int M, int N, int K)
{
    const int BM = 128, BN = 128, BK = 16;
    __shared__ float As[BK][BM];
    __shared__ float Bs[BK][BN];

    const int tid  = threadIdx.x;
    const int row0 = blockIdx.y * BM;
    const int col0 = blockIdx.x * BN;

    const int tx = tid & 15;   // 0..15 -> columns
    const int ty = tid >> 4;   // 0..15 -> rows

    float acc[8][8];
#pragma unroll
    for (int i = 0; i < 8; i++)
#pragma unroll
        for (int j = 0; j < 8; j++) acc[i][j] = 0.f;

    const int nkt = K / BK;
    for (int kt = 0; kt < nkt; kt++) {
        // load A tile (128x16) transposed into As[k][m]
#pragma unroll
        for (int it = 0; it < 2; it++) {
            int idx = tid + it * 256;          // 0..511 float4 slots
            int ar  = idx >> 2;                // row in tile
            int ac  = (idx & 3) << 2;          // col (k) in tile
            float4 v = make_float4(0.f, 0.f, 0.f, 0.f);
            int gr = row0 + ar;
            if (gr < M)
                v = *(const float4*)&A[(size_t)gr * K + kt * BK + ac];
            As[ac + 0][ar] = v.x;
            As[ac + 1][ar] = v.y;
            As[ac + 2][ar] = v.z;
            As[ac + 3][ar] = v.w;

            int br = idx >> 5;                 // row (k) in B tile
            int bc = (idx & 31) << 2;          // col in B tile
            float4 w = *(const float4*)&B[(size_t)(kt * BK + br) * N + col0 + bc];
            *(float4*)&Bs[br][bc] = w;
        }
        __syncthreads();

#pragma unroll
        for (int kk = 0; kk < BK; kk++) {
            float a[8], b[8];
#pragma unroll
            for (int i = 0; i < 8; i++) a[i] = As[kk][ty * 8 + i];
#pragma unroll
            for (int j = 0; j < 8; j++) b[j] = Bs[kk][tx * 8 + j];
#pragma unroll
            for (int i = 0; i < 8; i++)
#pragma unroll
                for (int j = 0; j < 8; j++)
                    acc[i][j] = fmaf(a[i], b[j], acc[i][j]);
        }
        __syncthreads();
    }

    // epilogue: add bias, store
    float bsv[8];
#pragma unroll
    for (int j = 0; j < 8; j++) bsv[j] = bias[col0 + tx * 8 + j];

#pragma unroll
    for (int i = 0; i < 8; i++) {
        int gr = row0 + ty * 8 + i;
        if (gr < M) {
#pragma unroll
            for (int j = 0; j < 8; j += 4) {
                float4 v;
                v.x = acc[i][j + 0] + bsv[j + 0];
                v.y = acc[i][j + 1] + bsv[j + 1];
                v.z = acc[i][j + 2] + bsv[j + 2];
                v.w = acc[i][j + 3] + bsv[j + 3];
                *(float4*)&C[(size_t)gr * N + col0 + tx * 8 + j] = v;
            }
        }
    }
}

// ---------------- fused softmax + bilinear sampling ----------------
// One warp per (n, q, h); lane = channel d (0..31).
__global__ __launch_bounds__(256)
void msda_sample(const float* __restrict__ value,
                 const float* __restrict__ off,
                 const float* __restrict__ awl,
                 const float* __restrict__ refp,
                 float* __restrict__ out)
{
    const unsigned FULL = 0xffffffffu;
    int gwarp = (blockIdx.x * blockDim.x + threadIdx.x) >> 5;
    int lane  = threadIdx.x & 31;
    if (gwarp >= NB * LQ * NH) return;

    int h  = gwarp % NH;
    int nq = gwarp / NH;          // n*LQ + q
    int n  = nq / LQ;

    // ---- softmax over 32 logits (lane i holds logit i) ----
    float logit = awl[(size_t)nq * (NH * NL * NP) + h * (NL * NP) + lane];
    float m = logit;
#pragma unroll
    for (int s = 16; s > 0; s >>= 1) m = fmaxf(m, __shfl_xor_sync(FULL, m, s));
    float e = __expf(logit - m);
    float ssum = e;
#pragma unroll
    for (int s = 16; s > 0; s >>= 1) ssum += __shfl_xor_sync(FULL, ssum, s);
    float aw = e / ssum;

    // ---- per-point offsets (lane p holds point p's (ox,oy)) ----
    float2 o2 = ((const float2*)(off + (size_t)nq * (NH * NL * NP * 2) + h * (NL * NP * 2)))[lane];

    // ---- reference points (lanes 0..3 hold z = 0..3) ----
    float2 r2 = make_float2(0.f, 0.f);
    if (lane < NZ)
        r2 = ((const float2*)(refp + (size_t)nq * NZ * 2))[lane];

    const int   Hs[4] = {64, 32, 16, 8};
    const int   Ws[4] = {176, 88, 44, 22};
    const int   St[4] = {0, 11264, 14080, 14784};

    const float* vbase = value + (size_t)n * LEN_IN * (NH * DH) + h * DH + lane;
    const int stride = NH * DH;  // 256 floats between pixels

    float acc = 0.f;
#pragma unroll
    for (int l = 0; l < NL; l++) {
        const int W = Ws[l], H = Hs[l];
        const float* vb = vbase + (size_t)St[l] * stride;
        const float fW = (float)W, fH = (float)H;
#pragma unroll
        for (int p = 0; p < NP; p++) {
            const int pi = l * NP + p;
            float ox = __shfl_sync(FULL, o2.x, pi);
            float oy = __shfl_sync(FULL, o2.y, pi);
            float a  = __shfl_sync(FULL, aw, pi);
            float rx = __shfl_sync(FULL, r2.x, p & (NZ - 1));
            float ry = __shfl_sync(FULL, r2.y, p & (NZ - 1));

            // loc*W - 0.5 with normalization folded: x = rx*W + ox - 0.5
            float x = fmaf(rx, fW, ox) - 0.5f;
            float y = fmaf(ry, fH, oy) - 0.5f;
            float xf = floorf(x), yf = floorf(y);
            int x0 = (int)xf, y0 = (int)yf;
            float wx = x - xf, wy = y - yf;
            float w0x = 1.f - wx, w0y = 1.f - wy;

            float sacc = 0.f;
            bool inx0 = ((unsigned)x0 < (unsigned)W);
            bool inx1 = ((unsigned)(x0 + 1) < (unsigned)W);
            bool iny0 = ((unsigned)y0 < (unsigned)H);
            bool iny1 = ((unsigned)(y0 + 1) < (unsigned)H);

            if (iny0) {
                int rb = y0 * W;
                if (inx0) sacc = fmaf(w0x * w0y, vb[(size_t)(rb + x0) * stride], sacc);
                if (inx1) sacc = fmaf(wx  * w0y, vb[(size_t)(rb + x0 + 1) * stride], sacc);
            }
            if (iny1) {
                int rb = (y0 + 1) * W;
                if (inx0) sacc = fmaf(w0x * wy, vb[(size_t)(rb + x0) * stride], sacc);
                if (inx1) sacc = fmaf(wx  * wy, vb[(size_t)(rb + x0 + 1) * stride], sacc);
            }
            acc = fmaf(a, sacc, acc);
        }
    }

    out[(size_t)nq * DM + h * DH + lane] = acc;
}

// ---------------- launch ----------------
extern "C" void kernel_launch(void* const* d_in, const int* in_sizes, int n_in,
                              void* d_out, int out_size)
{
    const float* query   = (const float*)d_in[0];
    // d_in[1] = query_pos (unused by reference)
    const float* refp    = (const float*)d_in[2];
    const float* in_flat = (const float*)d_in[3];
    // d_in[4] spatial shapes, d_in[5] level start (compile-time constants here)
    const float* Wv = (const float*)d_in[6];
    const float* bv = (const float*)d_in[7];
    const float* Wo = (const float*)d_in[8];
    const float* bo = (const float*)d_in[9];
    const float* Wa = (const float*)d_in[10];
    const float* ba = (const float*)d_in[11];
    float* out = (float*)d_out;

    float* val_s; cudaGetSymbolAddress((void**)&val_s, g_value);
    float* off_s; cudaGetSymbolAddress((void**)&off_s, g_off);
    float* awl_s; cudaGetSymbolAddress((void**)&awl_s, g_awl);

    const int Mv = NB * LEN_IN;   // 119680
    const int Mq = NB * LQ;       // 20000

    // value = input_flatten @ Wv + bv   (119680 x 256)
    {
        dim3 grid(DM / 128, (Mv + 127) / 128);
        sgemm_bias<<<grid, 256>>>(in_flat, Wv, bv, val_s, Mv, DM, DM);
    }
    // off = query @ Wo + bo   (20000 x 512)
    {
        dim3 grid((NH * NL * NP * 2) / 128, (Mq + 127) / 128);
        sgemm_bias<<<grid, 256>>>(query, Wo, bo, off_s, Mq, NH * NL * NP * 2, DM);
    }
    // logits = query @ Wa + ba  (20000 x 256)
    {
        dim3 grid((NH * NL * NP) / 128, (Mq + 127) / 128);
        sgemm_bias<<<grid, 256>>>(query, Wa, ba, awl_s, Mq, NH * NL * NP, DM);
    }
    // fused softmax + sampling, one warp per (n,q,h)
    {
        int warps = NB * LQ * NH;              // 160000
        int blocks = (warps + 7) / 8;          // 256 threads = 8 warps
        msda_sample<<<blocks, 256>>>(val_s, off_s, awl_s, refp, out);
    }
}

// round 2
// speedup vs baseline: 1.7237x; 1.7237x over previous
#include <cuda_runtime.h>
#include <cstdint>

// ---------------- problem constants ----------------
#define NB      8
#define LQ      2500
#define DM      256
#define NH      8
#define NL      4
#define NP      8
#define NZ      4
#define DH      32
#define LEN_IN  14960

// scratch
__device__ float g_value[(size_t)NB * LEN_IN * DM];           // 119680 x 256
__device__ float g_off  [(size_t)NB * LQ * NH * NL * NP * 2]; // 20000 x 512
__device__ float g_awl  [(size_t)NB * LQ * NH * NL * NP];     // 20000 x 256

__device__ __forceinline__ float to_tf32(float x) {
    float r;
    asm("cvt.rna.tf32.f32 %0, %1;" : "=f"(r) : "f"(x));
    return r;
}

// ---------------- tf32 tensor-core GEMM with bias ----------------
// C(MxN) = A(MxK) @ B(KxN) + bias.  BM=BN=128, BK=16, 256 threads (8 warps).
// Warp grid 4x2; warp tile 32x64 = 2 (m16) x 8 (n8) mma tiles, 2 k8 steps/iter.
// N % 128 == 0, K % 16 == 0 assumed; M guarded.
__global__ __launch_bounds__(256)
void gemm_tf32(const float* __restrict__ A,
               const float* __restrict__ B,
               const float* __restrict__ bias,
               float* __restrict__ C,
               int M, int N, int K)
{
    const int LDS_ = 136;                 // stride pad: bank = 8*tig + g, conflict-free
    __shared__ float As[16][LDS_];        // [k][m]
    __shared__ float Bs[16][LDS_];        // [k][n]

    const int tid   = threadIdx.x;
    const int row0  = blockIdx.y * 128;
    const int col0  = blockIdx.x * 128;
    const int warp  = tid >> 5;
    const int lane  = tid & 31;
    const int g     = lane >> 2;          // groupID 0..7
    const int tig   = lane & 3;           // thread-in-group 0..3
    const int warpM = warp & 3;           // 0..3
    const int warpN = warp >> 2;          // 0..1
    const int mrow  = warpM * 32;         // warp row base within tile
    const int ncol  = warpN * 64;         // warp col base within tile

    float acc[2][8][4];
#pragma unroll
    for (int i = 0; i < 2; i++)
#pragma unroll
        for (int j = 0; j < 8; j++)
#pragma unroll
            for (int c = 0; c < 4; c++) acc[i][j][c] = 0.f;

    const int nkt = K / 16;
    for (int kt = 0; kt < nkt; kt++) {
#pragma unroll
        for (int it = 0; it < 2; it++) {
            int idx = tid + it * 256;     // 0..511 float4 slots
            // A: 128 rows x 16 k -> transposed store As[k][m]
            int ar = idx >> 2;            // m row in tile
            int ac = (idx & 3) << 2;      // k col in tile
            float4 v = make_float4(0.f, 0.f, 0.f, 0.f);
            int gr = row0 + ar;
            if (gr < M)
                v = *(const float4*)&A[(size_t)gr * K + kt * 16 + ac];
            As[ac + 0][ar] = to_tf32(v.x);
            As[ac + 1][ar] = to_tf32(v.y);
            As[ac + 2][ar] = to_tf32(v.z);
            As[ac + 3][ar] = to_tf32(v.w);
            // B: 16 k-rows x 128 cols -> direct store Bs[k][n]
            int br = idx >> 5;
            int bc = (idx & 31) << 2;
            float4 w = *(const float4*)&B[(size_t)(kt * 16 + br) * N + col0 + bc];
            Bs[br][bc + 0] = to_tf32(w.x);
            Bs[br][bc + 1] = to_tf32(w.y);
            Bs[br][bc + 2] = to_tf32(w.z);
            Bs[br][bc + 3] = to_tf32(w.w);
        }
        __syncthreads();

#pragma unroll
        for (int ks = 0; ks < 2; ks++) {
            const int k0 = ks * 8;
            uint32_t afr[2][4];
#pragma unroll
            for (int mt = 0; mt < 2; mt++) {
                int rb = mrow + mt * 16;
                afr[mt][0] = __float_as_uint(As[k0 + tig    ][rb + g    ]);
                afr[mt][1] = __float_as_uint(As[k0 + tig    ][rb + g + 8]);
                afr[mt][2] = __float_as_uint(As[k0 + tig + 4][rb + g    ]);
                afr[mt][3] = __float_as_uint(As[k0 + tig + 4][rb + g + 8]);
            }
            uint32_t bfr[8][2];
#pragma unroll
            for (int nt = 0; nt < 8; nt++) {
                int cb = ncol + nt * 8;
                bfr[nt][0] = __float_as_uint(Bs[k0 + tig    ][cb + g]);
                bfr[nt][1] = __float_as_uint(Bs[k0 + tig + 4][cb + g]);
            }
#pragma unroll
            for (int mt = 0; mt < 2; mt++)
#pragma unroll
                for (int nt = 0; nt < 8; nt++) {
                    asm volatile(
                        "mma.sync.aligned.m16n8k8.row.col.f32.tf32.tf32.f32 "
                        "{%0,%1,%2,%3}, {%4,%5,%6,%7}, {%8,%9}, {%0,%1,%2,%3};"
                        : "+f"(acc[mt][nt][0]), "+f"(acc[mt][nt][1]),
                          "+f"(acc[mt][nt][2]), "+f"(acc[mt][nt][3])
                        : "r"(afr[mt][0]), "r"(afr[mt][1]),
                          "r"(afr[mt][2]), "r"(afr[mt][3]),
                          "r"(bfr[nt][0]), "r"(bfr[nt][1]));
                }
        }
        __syncthreads();
    }

    // epilogue
#pragma unroll
    for (int mt = 0; mt < 2; mt++) {
#pragma unroll
        for (int nt = 0; nt < 8; nt++) {
            int c = col0 + ncol + nt * 8 + tig * 2;
            float b0 = bias[c], b1 = bias[c + 1];
            int r0 = row0 + mrow + mt * 16 + g;
            if (r0 < M) {
                float2 v0 = make_float2(acc[mt][nt][0] + b0, acc[mt][nt][1] + b1);
                *(float2*)&C[(size_t)r0 * N + c] = v0;
            }
            int r1 = r0 + 8;
            if (r1 < M) {
                float2 v1 = make_float2(acc[mt][nt][2] + b0, acc[mt][nt][3] + b1);
                *(float2*)&C[(size_t)r1 * N + c] = v1;
            }
        }
    }
}

// ---------------- fused softmax + bilinear sampling (v2) ----------------
// One warp per (n, q, h).
// Phase 1: lane p computes point p's 4 gather offsets + 4 aw-premultiplied weights.
// Phase 2: lane = channel; per point broadcast (8 shfl) + 4 loads + 4 fma.
__global__ __launch_bounds__(256)
void msda_sample2(const float* __restrict__ value,
                  const float* __restrict__ off,
                  const float* __restrict__ awl,
                  const float* __restrict__ refp,
                  float* __restrict__ out)
{
    const unsigned FULL = 0xffffffffu;
    int gwarp = (blockIdx.x * blockDim.x + threadIdx.x) >> 5;
    int lane  = threadIdx.x & 31;
    if (gwarp >= NB * LQ * NH) return;

    int h  = gwarp % NH;
    int nq = gwarp / NH;
    int n  = nq / LQ;

    // softmax over 32 logits (lane = point index)
    float logit = awl[(size_t)nq * (NH * NL * NP) + h * (NL * NP) + lane];
    float m = logit;
#pragma unroll
    for (int s = 16; s > 0; s >>= 1) m = fmaxf(m, __shfl_xor_sync(FULL, m, s));
    float e = __expf(logit - m);
    float ssum = e;
#pragma unroll
    for (int s = 16; s > 0; s >>= 1) ssum += __shfl_xor_sync(FULL, ssum, s);
    float aw = e / ssum;

    // per-point precompute (lane p == point p: level l = lane>>3, z = lane&3)
    float2 o2 = ((const float2*)(off + (size_t)nq * (NH * NL * NP * 2) + h * (NL * NP * 2)))[lane];
    int l = lane >> 3;
    float2 r2 = ((const float2*)(refp + (size_t)nq * NZ * 2))[lane & 3];
    int W = 176 >> l;
    int H = 64 >> l;
    int St = ((l > 0) ? 11264 : 0) + ((l > 1) ? 2816 : 0) + ((l > 2) ? 704 : 0);

    float x = fmaf(r2.x, (float)W, o2.x) - 0.5f;
    float y = fmaf(r2.y, (float)H, o2.y) - 0.5f;
    float xf = floorf(x), yf = floorf(y);
    int x0 = (int)xf, y0 = (int)yf;
    float wx = x - xf, wy = y - yf;
    float w00 = (1.f - wx) * (1.f - wy) * aw;
    float w01 = wx * (1.f - wy) * aw;
    float w10 = (1.f - wx) * wy * aw;
    float w11 = wx * wy * aw;

    bool ix0 = ((unsigned)x0       < (unsigned)W);
    bool ix1 = ((unsigned)(x0 + 1) < (unsigned)W);
    bool iy0 = ((unsigned)y0       < (unsigned)H);
    bool iy1 = ((unsigned)(y0 + 1) < (unsigned)H);

    int i00 = 0, i01 = 0, i10 = 0, i11 = 0;
    if (ix0 && iy0) i00 = (St + y0 * W + x0) * DM;           else w00 = 0.f;
    if (ix1 && iy0) i01 = (St + y0 * W + x0 + 1) * DM;       else w01 = 0.f;
    if (ix0 && iy1) i10 = (St + (y0 + 1) * W + x0) * DM;     else w10 = 0.f;
    if (ix1 && iy1) i11 = (St + (y0 + 1) * W + x0 + 1) * DM; else w11 = 0.f;

    // gather phase: lane = channel
    const float* vb = value + (size_t)n * LEN_IN * DM + h * DH + lane;
    float acc = 0.f;
#pragma unroll 8
    for (int p = 0; p < 32; p++) {
        int   j0 = __shfl_sync(FULL, i00, p);
        int   j1 = __shfl_sync(FULL, i01, p);
        int   j2 = __shfl_sync(FULL, i10, p);
        int   j3 = __shfl_sync(FULL, i11, p);
        float u0 = __shfl_sync(FULL, w00, p);
        float u1 = __shfl_sync(FULL, w01, p);
        float u2 = __shfl_sync(FULL, w10, p);
        float u3 = __shfl_sync(FULL, w11, p);
        acc = fmaf(u0, __ldg(vb + j0), acc);
        acc = fmaf(u1, __ldg(vb + j1), acc);
        acc = fmaf(u2, __ldg(vb + j2), acc);
        acc = fmaf(u3, __ldg(vb + j3), acc);
    }

    out[(size_t)nq * DM + h * DH + lane] = acc;
}

// ---------------- launch ----------------
extern "C" void kernel_launch(void* const* d_in, const int* in_sizes, int n_in,
                              void* d_out, int out_size)
{
    const float* query   = (const float*)d_in[0];
    const float* refp    = (const float*)d_in[2];
    const float* in_flat = (const float*)d_in[3];
    const float* Wv = (const float*)d_in[6];
    const float* bv = (const float*)d_in[7];
    const float* Wo = (const float*)d_in[8];
    const float* bo = (const float*)d_in[9];
    const float* Wa = (const float*)d_in[10];
    const float* ba = (const float*)d_in[11];
    float* out = (float*)d_out;

    float* val_s; cudaGetSymbolAddress((void**)&val_s, g_value);
    float* off_s; cudaGetSymbolAddress((void**)&off_s, g_off);
    float* awl_s; cudaGetSymbolAddress((void**)&awl_s, g_awl);

    const int Mv = NB * LEN_IN;   // 119680
    const int Mq = NB * LQ;       // 20000

    {   // value = input_flatten @ Wv + bv
        dim3 grid(DM / 128, (Mv + 127) / 128);
        gemm_tf32<<<grid, 256>>>(in_flat, Wv, bv, val_s, Mv, DM, DM);
    }
    {   // off = query @ Wo + bo
        dim3 grid((NH * NL * NP * 2) / 128, (Mq + 127) / 128);
        gemm_tf32<<<grid, 256>>>(query, Wo, bo, off_s, Mq, NH * NL * NP * 2, DM);
    }
    {   // logits = query @ Wa + ba
        dim3 grid((NH * NL * NP) / 128, (Mq + 127) / 128);
        gemm_tf32<<<grid, 256>>>(query, Wa, ba, awl_s, Mq, NH * NL * NP, DM);
    }
    {   // fused softmax + sampling
        int warps = NB * LQ * NH;
        int blocks = (warps + 7) / 8;
        msda_sample2<<<blocks, 256>>>(val_s, off_s, awl_s, refp, out);
    }
}

// round 3
// speedup vs baseline: 2.5029x; 1.4520x over previous
#include <cuda_runtime.h>
#include <cstdint>

// ---------------- problem constants ----------------
#define NB      8
#define LQ      2500
#define DM      256
#define NH      8
#define NL      4
#define NP      8
#define NZ      4
#define DH      32
#define LEN_IN  14960

// scratch
__device__ float g_value[(size_t)NB * LEN_IN * DM];           // 119680 x 256
__device__ float g_off  [(size_t)NB * LQ * NH * NL * NP * 2]; // 20000 x 512
__device__ float g_awl  [(size_t)NB * LQ * NH * NL * NP];     // 20000 x 256

__device__ __forceinline__ float to_tf32(float x) {
    float r;
    asm("cvt.rna.tf32.f32 %0, %1;" : "=f"(r) : "f"(x));
    return r;
}

__device__ __forceinline__ uint32_t smem_u32(const void* p) {
    return (uint32_t)__cvta_generic_to_shared(p);
}

__device__ __forceinline__ void cp_async16(void* dst, const void* src, bool pred) {
    int sz = pred ? 16 : 0;
    asm volatile("cp.async.ca.shared.global [%0], [%1], 16, %2;\n"
                 :: "r"(smem_u32(dst)), "l"(src), "r"(sz));
}

// ---------------- tf32 tensor-core GEMM, cp.async double-buffered ----------------
// C(MxN) = A(MxK) @ B(KxN) + bias.  BM=BN=128, BK=16, 256 threads (8 warps).
// Warp grid 4x2; warp tile 32x64. N%128==0, K%16==0 assumed; M guarded.
#define A_LD 20     // A smem row stride (floats): banks (20g+tig)%32 all-distinct
#define B_LD 136    // B smem row stride (floats): banks (8tig+g)%32 all-distinct
#define A_BUF (128 * A_LD)
#define B_BUF (16 * B_LD)

__global__ __launch_bounds__(256)
void gemm_tf32_db(const float* __restrict__ A,
                  const float* __restrict__ B,
                  const float* __restrict__ bias,
                  float* __restrict__ C,
                  int M, int N, int K)
{
    __shared__ float As[2 * A_BUF];   // [buf][m][k] rows of 16 (pad 20)
    __shared__ float Bs[2 * B_BUF];   // [buf][k][n] rows of 128 (pad 136)

    const int tid   = threadIdx.x;
    const int row0  = blockIdx.y * 128;
    const int col0  = blockIdx.x * 128;
    const int warp  = tid >> 5;
    const int lane  = tid & 31;
    const int g     = lane >> 2;
    const int tig   = lane & 3;
    const int mrow  = (warp & 3) * 32;
    const int ncol  = (warp >> 1 >> 1) * 64;   // warpN = warp>>2

    float acc[2][8][4];
#pragma unroll
    for (int i = 0; i < 2; i++)
#pragma unroll
        for (int j = 0; j < 8; j++)
#pragma unroll
            for (int c = 0; c < 4; c++) acc[i][j][c] = 0.f;

    // staging maps (per thread: 2 A float4, 2 B float4)
    const int a_r0 = tid >> 2, a_c = (tid & 3) << 2;          // +64 rows for i=1
    const int b_r0 = tid >> 5, b_c = (tid & 31) << 2;         // +8 rows for i=1

    const int nkt = K / 16;

    auto stage = [&](int kt, int buf) {
        float* ab = As + buf * A_BUF;
        float* bb = Bs + buf * B_BUF;
#pragma unroll
        for (int i = 0; i < 2; i++) {
            int ar = a_r0 + i * 64;
            int gr = row0 + ar;
            cp_async16(&ab[ar * A_LD + a_c],
                       &A[(size_t)min(gr, M - 1) * K + kt * 16 + a_c], gr < M);
            int br = b_r0 + i * 8;
            cp_async16(&bb[br * B_LD + b_c],
                       &B[(size_t)(kt * 16 + br) * N + col0 + b_c], true);
        }
    };

    stage(0, 0);
    asm volatile("cp.async.commit_group;\n");

    for (int kt = 0; kt < nkt; kt++) {
        int cb = kt & 1;
        if (kt + 1 < nkt) stage(kt + 1, cb ^ 1);
        asm volatile("cp.async.commit_group;\n");
        asm volatile("cp.async.wait_group 1;\n");
        __syncthreads();

        const float* ab = As + cb * A_BUF;
        const float* bb = Bs + cb * B_BUF;
#pragma unroll
        for (int ks = 0; ks < 2; ks++) {
            const int k0 = ks * 8;
            uint32_t afr[2][4];
#pragma unroll
            for (int mt = 0; mt < 2; mt++) {
                int rb = mrow + mt * 16;
                afr[mt][0] = __float_as_uint(to_tf32(ab[(rb + g    ) * A_LD + k0 + tig    ]));
                afr[mt][1] = __float_as_uint(to_tf32(ab[(rb + g + 8) * A_LD + k0 + tig    ]));
                afr[mt][2] = __float_as_uint(to_tf32(ab[(rb + g    ) * A_LD + k0 + tig + 4]));
                afr[mt][3] = __float_as_uint(to_tf32(ab[(rb + g + 8) * A_LD + k0 + tig + 4]));
            }
            uint32_t bfr[8][2];
#pragma unroll
            for (int nt = 0; nt < 8; nt++) {
                int cbn = ncol + nt * 8;
                bfr[nt][0] = __float_as_uint(to_tf32(bb[(k0 + tig    ) * B_LD + cbn + g]));
                bfr[nt][1] = __float_as_uint(to_tf32(bb[(k0 + tig + 4) * B_LD + cbn + g]));
            }
#pragma unroll
            for (int mt = 0; mt < 2; mt++)
#pragma unroll
                for (int nt = 0; nt < 8; nt++) {
                    asm volatile(
                        "mma.sync.aligned.m16n8k8.row.col.f32.tf32.tf32.f32 "
                        "{%0,%1,%2,%3}, {%4,%5,%6,%7}, {%8,%9}, {%0,%1,%2,%3};"
                        : "+f"(acc[mt][nt][0]), "+f"(acc[mt][nt][1]),
                          "+f"(acc[mt][nt][2]), "+f"(acc[mt][nt][3])
                        : "r"(afr[mt][0]), "r"(afr[mt][1]),
                          "r"(afr[mt][2]), "r"(afr[mt][3]),
                          "r"(bfr[nt][0]), "r"(bfr[nt][1]));
                }
        }
        __syncthreads();
    }

    // epilogue
#pragma unroll
    for (int mt = 0; mt < 2; mt++) {
#pragma unroll
        for (int nt = 0; nt < 8; nt++) {
            int c = col0 + ncol + nt * 8 + tig * 2;
            float b0 = bias[c], b1 = bias[c + 1];
            int r0 = row0 + mrow + mt * 16 + g;
            if (r0 < M) {
                float2 v0 = make_float2(acc[mt][nt][0] + b0, acc[mt][nt][1] + b1);
                *(float2*)&C[(size_t)r0 * N + c] = v0;
            }
            int r1 = r0 + 8;
            if (r1 < M) {
                float2 v1 = make_float2(acc[mt][nt][2] + b0, acc[mt][nt][3] + b1);
                *(float2*)&C[(size_t)r1 * N + c] = v1;
            }
        }
    }
}

// ---------------- fused softmax + bilinear sampling (v3) ----------------
// One warp per (n, q, h).
// Phase 1: lane p computes point p's 4 gather indices + 4 aw-premultiplied weights.
// Phase 2: lane = (q4 = point-subgroup 0..3) x (c8 = channel-quad 0..7).
//          One LDG.128 serves 4 points at once; 2 variable-src shfl per point.
// Phase 3: cross-subgroup reduction (8 shfl), lanes 0..7 write float4.
__global__ __launch_bounds__(256)
void msda_sample3(const float* __restrict__ value,
                  const float* __restrict__ off,
                  const float* __restrict__ awl,
                  const float* __restrict__ refp,
                  float* __restrict__ out)
{
    const unsigned FULL = 0xffffffffu;
    int gwarp = (blockIdx.x * blockDim.x + threadIdx.x) >> 5;
    int lane  = threadIdx.x & 31;
    if (gwarp >= NB * LQ * NH) return;

    int h  = gwarp % NH;
    int nq = gwarp / NH;
    int n  = nq / LQ;

    // softmax over 32 logits (lane = point index)
    float logit = awl[(size_t)nq * (NH * NL * NP) + h * (NL * NP) + lane];
    float m = logit;
#pragma unroll
    for (int s = 16; s > 0; s >>= 1) m = fmaxf(m, __shfl_xor_sync(FULL, m, s));
    float e = __expf(logit - m);
    float ssum = e;
#pragma unroll
    for (int s = 16; s > 0; s >>= 1) ssum += __shfl_xor_sync(FULL, ssum, s);
    float aw = e / ssum;

    // per-point precompute (lane p == point p: level l = lane>>3, z = lane&3)
    float2 o2 = ((const float2*)(off + (size_t)nq * (NH * NL * NP * 2) + h * (NL * NP * 2)))[lane];
    int l = lane >> 3;
    float2 r2 = ((const float2*)(refp + (size_t)nq * NZ * 2))[lane & 3];
    int W = 176 >> l;
    int H = 64 >> l;
    int St = ((l > 0) ? 11264 : 0) + ((l > 1) ? 2816 : 0) + ((l > 2) ? 704 : 0);

    float x = fmaf(r2.x, (float)W, o2.x) - 0.5f;
    float y = fmaf(r2.y, (float)H, o2.y) - 0.5f;
    float xf = floorf(x), yf = floorf(y);
    int x0 = (int)xf, y0 = (int)yf;
    float wx = x - xf, wy = y - yf;
    float w00 = (1.f - wx) * (1.f - wy) * aw;
    float w01 = wx * (1.f - wy) * aw;
    float w10 = (1.f - wx) * wy * aw;
    float w11 = wx * wy * aw;

    bool ix0 = ((unsigned)x0       < (unsigned)W);
    bool ix1 = ((unsigned)(x0 + 1) < (unsigned)W);
    bool iy0 = ((unsigned)y0       < (unsigned)H);
    bool iy1 = ((unsigned)(y0 + 1) < (unsigned)H);

    int i00 = 0, i01 = 0, i10 = 0, i11 = 0;     // float4-granule indices
    if (ix0 && iy0) i00 = (St + y0 * W + x0) * (DM / 4);           else w00 = 0.f;
    if (ix1 && iy0) i01 = (St + y0 * W + x0 + 1) * (DM / 4);       else w01 = 0.f;
    if (ix0 && iy1) i10 = (St + (y0 + 1) * W + x0) * (DM / 4);     else w10 = 0.f;
    if (ix1 && iy1) i11 = (St + (y0 + 1) * W + x0 + 1) * (DM / 4); else w11 = 0.f;

    // gather phase: lane = q4*8 + c8
    int q4 = lane >> 3;
    int c8 = lane & 7;
    const float4* vb4 = (const float4*)(value + (size_t)n * LEN_IN * DM + h * DH) + c8;

    float4 acc4 = make_float4(0.f, 0.f, 0.f, 0.f);
#pragma unroll
    for (int pb = 0; pb < 32; pb += 4) {
        int src = pb + q4;
        int j; float u; float4 v;

        j = __shfl_sync(FULL, i00, src); u = __shfl_sync(FULL, w00, src);
        v = __ldg(vb4 + j);
        acc4.x = fmaf(u, v.x, acc4.x); acc4.y = fmaf(u, v.y, acc4.y);
        acc4.z = fmaf(u, v.z, acc4.z); acc4.w = fmaf(u, v.w, acc4.w);

        j = __shfl_sync(FULL, i01, src); u = __shfl_sync(FULL, w01, src);
        v = __ldg(vb4 + j);
        acc4.x = fmaf(u, v.x, acc4.x); acc4.y = fmaf(u, v.y, acc4.y);
        acc4.z = fmaf(u, v.z, acc4.z); acc4.w = fmaf(u, v.w, acc4.w);

        j = __shfl_sync(FULL, i10, src); u = __shfl_sync(FULL, w10, src);
        v = __ldg(vb4 + j);
        acc4.x = fmaf(u, v.x, acc4.x); acc4.y = fmaf(u, v.y, acc4.y);
        acc4.z = fmaf(u, v.z, acc4.z); acc4.w = fmaf(u, v.w, acc4.w);

        j = __shfl_sync(FULL, i11, src); u = __shfl_sync(FULL, w11, src);
        v = __ldg(vb4 + j);
        acc4.x = fmaf(u, v.x, acc4.x); acc4.y = fmaf(u, v.y, acc4.y);
        acc4.z = fmaf(u, v.z, acc4.z); acc4.w = fmaf(u, v.w, acc4.w);
    }

    // reduce across the 4 point-subgroups (lanes xor 8, 16)
#pragma unroll
    for (int s = 8; s <= 16; s <<= 1) {
        acc4.x += __shfl_xor_sync(FULL, acc4.x, s);
        acc4.y += __shfl_xor_sync(FULL, acc4.y, s);
        acc4.z += __shfl_xor_sync(FULL, acc4.z, s);
        acc4.w += __shfl_xor_sync(FULL, acc4.w, s);
    }

    if (lane < 8)
        ((float4*)(out + (size_t)nq * DM + h * DH))[lane] = acc4;
}

// ---------------- launch ----------------
extern "C" void kernel_launch(void* const* d_in, const int* in_sizes, int n_in,
                              void* d_out, int out_size)
{
    const float* query   = (const float*)d_in[0];
    const float* refp    = (const float*)d_in[2];
    const float* in_flat = (const float*)d_in[3];
    const float* Wv = (const float*)d_in[6];
    const float* bv = (const float*)d_in[7];
    const float* Wo = (const float*)d_in[8];
    const float* bo = (const float*)d_in[9];
    const float* Wa = (const float*)d_in[10];
    const float* ba = (const float*)d_in[11];
    float* out = (float*)d_out;

    float* val_s; cudaGetSymbolAddress((void**)&val_s, g_value);
    float* off_s; cudaGetSymbolAddress((void**)&off_s, g_off);
    float* awl_s; cudaGetSymbolAddress((void**)&awl_s, g_awl);

    const int Mv = NB * LEN_IN;   // 119680
    const int Mq = NB * LQ;       // 20000

    {   // value = input_flatten @ Wv + bv
        dim3 grid(DM / 128, (Mv + 127) / 128);
        gemm_tf32_db<<<grid, 256>>>(in_flat, Wv, bv, val_s, Mv, DM, DM);
    }
    {   // off = query @ Wo + bo
        dim3 grid((NH * NL * NP * 2) / 128, (Mq + 127) / 128);
        gemm_tf32_db<<<grid, 256>>>(query, Wo, bo, off_s, Mq, NH * NL * NP * 2, DM);
    }
    {   // logits = query @ Wa + ba
        dim3 grid((NH * NL * NP) / 128, (Mq + 127) / 128);
        gemm_tf32_db<<<grid, 256>>>(query, Wa, ba, awl_s, Mq, NH * NL * NP, DM);
    }
    {   // fused softmax + sampling
        int warps = NB * LQ * NH;
        int blocks = (warps + 7) / 8;
        msda_sample3<<<blocks, 256>>>(val_s, off_s, awl_s, refp, out);
    }
}